// round 7
// baseline (speedup 1.0000x reference)
#include <cuda_runtime.h>
#include <cuda_fp16.h>
#include <math.h>

#define KNOTS 64
#define WCOLS 7168          // 7 paths * 32 u * 32 w
#define MAXN  4096
#define MAXE  32768

typedef unsigned long long ull;

// ---------------- scratch (device globals; no allocation allowed) ----------------
__device__ float g_wtab[(size_t)KNOTS * WCOLS];   // fp32 table, scales folded in
__device__ float g_nodeacc[MAXN * 161];           // 160 sums + 1 count per node
__device__ int   g_binCount[KNOTS];               // zero-init at load; self-resetting per launch
__device__ int   g_binCursor[KNOTS];
__device__ int   g_perm[MAXE];

// ---------------- f32x2 helpers ----------------
__device__ __forceinline__ ull pk2(float lo, float hi) {
    ull r; asm("mov.b64 %0, {%1, %2};" : "=l"(r) : "f"(lo), "f"(hi)); return r;
}
__device__ __forceinline__ void upk2(ull v, float& lo, float& hi) {
    asm("mov.b64 {%0, %1}, %2;" : "=f"(lo), "=f"(hi) : "l"(v));
}
__device__ __forceinline__ void fma2(ull& d, ull a, ull b) {
    asm("fma.rn.f32x2 %0, %1, %2, %0;" : "+l"(d) : "l"(a), "l"(b));
}
__device__ __forceinline__ ull sub2(ull a, ull b) {   // a - b
    ull r; asm("sub.rn.f32x2 %0, %1, %2;" : "=l"(r) : "l"(a), "l"(b)); return r;
}

__device__ __forceinline__ int cell_of(float L) {
    float t = L * ((float)(KNOTS - 1) / 5.0f);
    int i = (int)floorf(t);
    if (i < 0) i = 0;
    if (i > KNOTS - 2) i = KNOTS - 2;
    return i;
}

// ---------------- kernel 1: build fp32 W(r) table + low-contention histogram ----------------
__global__ void k_build(const float* __restrict__ Wfc1, const float* __restrict__ Wfc2,
                        const float* __restrict__ len, int E) {
    __shared__ float sm_h[64][17];
    __shared__ int   sm_hist[KNOTS];
    const int t = threadIdx.x;
    const int kbase = blockIdx.x * 16;
    const int col = blockIdx.y * 256 + t;

    if (t < KNOTS) sm_hist[t] = 0;
    __syncthreads();

    {
        int gid = (blockIdx.y * gridDim.x + blockIdx.x) * 256 + t;
        int stride = gridDim.x * gridDim.y * 256;
        for (int e = gid; e < E; e += stride)
            atomicAdd(&sm_hist[cell_of(len[e])], 1);
    }

    for (int idx = t; idx < 16 * 64; idx += 256) {
        int kk = idx >> 6, c = idx & 63;
        float r = (float)(kbase + kk) * (5.0f / (float)(KNOTS - 1));
        float pre = 0.0f;
        #pragma unroll
        for (int j = 0; j < 8; j++) {
            float d = r - (float)j * (5.0f / 7.0f);
            float rad = expf(-d * d * 0.98f);
            pre += rad * Wfc1[j * 64 + c];
        }
        pre *= 0.35355339059327373f;                    // 1/sqrt(8)
        sm_h[c][kk] = pre / (1.0f + expf(-pre));        // silu
    }
    __syncthreads();

    if (t < KNOTS && sm_hist[t] > 0) atomicAdd(&g_binCount[t], sm_hist[t]);

    float acc[16];
    #pragma unroll
    for (int kk = 0; kk < 16; kk++) acc[kk] = 0.0f;
    #pragma unroll 4
    for (int c = 0; c < 64; c++) {
        float wv = __ldg(&Wfc2[c * WCOLS + col]);
        #pragma unroll
        for (int kk = 0; kk < 16; kk++) acc[kk] = fmaf(sm_h[c][kk], wv, acc[kk]);
    }
    float sc = (col < 4096) ? 0.015625f : 0.022097086912079608f;
    #pragma unroll
    for (int kk = 0; kk < 16; kk++)
        g_wtab[(size_t)(kbase + kk) * WCOLS + col] = acc[kk] * sc;
}

// ---------------- kernel 2: scan (1 warp, 64 bins) + self-reset of binCount ----------------
__global__ void k_scan() {
    int t = threadIdx.x;
    int v0 = g_binCount[2 * t], v1 = g_binCount[2 * t + 1];
    int s = v0 + v1;
    int x = s;
    #pragma unroll
    for (int o = 1; o < 32; o <<= 1) {
        int y = __shfl_up_sync(0xffffffffu, x, o);
        if (t >= o) x += y;
    }
    int excl = x - s;
    g_binCursor[2 * t]     = excl;
    g_binCursor[2 * t + 1] = excl + v0;
    g_binCount[2 * t] = 0;
    g_binCount[2 * t + 1] = 0;
}

// ---------------- kernel 3: two-level scatter + nodeacc zeroing ----------------
__global__ void k_scatterzero(const float* __restrict__ len, int E, int accTotal) {
    __shared__ int sCnt[KNOTS];
    __shared__ int sBase[KNOTS];
    const int t = threadIdx.x;
    const int gid = blockIdx.x * 256 + t;

    if (t < KNOTS) sCnt[t] = 0;

    for (int i = gid; i < accTotal; i += gridDim.x * 256) g_nodeacc[i] = 0.0f;
    __syncthreads();

    int e = -1, bin = 0, rank = 0;
    if (gid < E) {
        e = gid;
        bin = cell_of(len[e]);
        rank = atomicAdd(&sCnt[bin], 1);
    }
    __syncthreads();
    if (t < KNOTS) sBase[t] = (sCnt[t] > 0) ? atomicAdd(&g_binCursor[t], sCnt[t]) : 0;
    __syncthreads();
    if (e >= 0) g_perm[sBase[bin] + rank] = e;
}

// ---------------- kernel 4 (profiled slot): main edge kernel ----------------
// 1 warp per edge; lane = (wg = lane&7 -> 4 consecutive w; us = lane>>3 -> u stride 4).
// fp32 table read as ulonglong2 (LDG.128) -> direct f32x2 operands, zero cvt.
__global__ __launch_bounds__(256, 3) void k_edge(
        const float* __restrict__ x, const float* __restrict__ attr,
        const float* __restrict__ len, const int* __restrict__ src,
        const int* __restrict__ dst, int E) {
    __shared__ float2 tf2[8][32][11];   // features pre-duplicated as (v,v)
    const int warp = threadIdx.x >> 5, lane = threadIdx.x & 31;
    int eidx = blockIdx.x * 8 + warp;
    if (eidx >= E) return;
    int e = g_perm[eidx];

    int sn = src[e], dn = dst[e];
    float L = len[e];
    const float* ar = attr + e * 9;
    float y0  = ar[0];
    float y10 = ar[1], y11 = ar[2], y12 = ar[3];
    float y20 = ar[4], y21 = ar[5], y22 = ar[6], y23 = ar[7], y24 = ar[8];

    const float cA = 0.31622776601683794f;   // 1/sqrt(10)
    const float cB = 0.18257418583505536f;   // 1/sqrt(30)
    const float cC = 0.36514837167011072f;   // 2/sqrt(30)
    float M00 = -cB * y22 + cA * y24;
    float M01 =  cA * y20,  M02 = cA * y23;
    float M10 =  cA * y20,  M11 = -cB * y22 - cA * y24, M12 = cA * y21;
    float M20 =  cA * y23,  M21 = cA * y21,             M22 = cC * y22;

    const float* xr = x + (size_t)sn * 128;
    float sj = xr[lane];
    float v0 = xr[32 + 3 * lane], v1 = xr[33 + 3 * lane], v2 = xr[34 + 3 * lane];
    const float IS3 = 0.5773502691896258f;
    float2* tr = &tf2[warp][lane][0];
    float t00 = sj * y0;
    float t11 = (v0 * y10 + v1 * y11 + v2 * y12) * IS3;
    tr[0] = make_float2(t00, t00);
    tr[1] = make_float2(t11, t11);
    float sy = sj * IS3;
    tr[2] = make_float2(sy * y10, sy * y10);
    tr[3] = make_float2(sy * y11, sy * y11);
    tr[4] = make_float2(sy * y12, sy * y12);
    float yv = y0 * IS3;
    tr[5] = make_float2(v0 * yv, v0 * yv);
    tr[6] = make_float2(v1 * yv, v1 * yv);
    tr[7] = make_float2(v2 * yv, v2 * yv);
    float t12a = v0 * M00 + v1 * M10 + v2 * M20;
    float t12b = v0 * M01 + v1 * M11 + v2 * M21;
    float t12c = v0 * M02 + v1 * M12 + v2 * M22;
    tr[8]  = make_float2(t12a, t12a);
    tr[9]  = make_float2(t12b, t12b);
    tr[10] = make_float2(t12c, t12c);
    __syncwarp();

    float tp = L * ((float)(KNOTS - 1) / 5.0f);
    int ci = (int)floorf(tp);
    if (ci < 0) ci = 0;
    if (ci > KNOTS - 2) ci = KNOTS - 2;
    float f = tp - (float)ci;
    ull f2 = pk2(f, f);
    const float* r0 = g_wtab + (size_t)ci * WCOLS;
    const float* r1 = r0 + WCOLS;

    const int wg = lane & 7, us = lane >> 3;
    const int wb = wg * 4;

    // single accumulator bank: [col-pair]
    ull aS[2]    = {0ull, 0ull};
    ull aG[2]    = {0ull, 0ull};
    ull aV[3][2] = {{0ull,0ull},{0ull,0ull},{0ull,0ull}};

    #pragma unroll 2
    for (int j = 0; j < 8; j++) {
        int u = 4 * j + us;
        const ull* Fv = reinterpret_cast<const ull*>(&tf2[warp][u][0]);
        int ub = u * 32 + wb;
        const float* p0 = r0 + ub;
        const float* p1 = r1 + ub;
        ull W0, W1, F;

#define LOADP(P)                                                                      \
        {                                                                             \
            ulonglong2 _a = *reinterpret_cast<const ulonglong2*>(p0 + (P) * 1024);    \
            ulonglong2 _b = *reinterpret_cast<const ulonglong2*>(p1 + (P) * 1024);    \
            W0 = _a.x; fma2(W0, f2, sub2(_b.x, _a.x));                                \
            W1 = _a.y; fma2(W1, f2, sub2(_b.y, _a.y));                                \
        }

        LOADP(0); F = Fv[0]; fma2(aS[0], F, W0); fma2(aS[1], F, W1);
        LOADP(1); F = Fv[1]; fma2(aS[0], F, W0); fma2(aS[1], F, W1);
        LOADP(2); F = Fv[0]; fma2(aG[0], F, W0); fma2(aG[1], F, W1);
        LOADP(3); F = Fv[1]; fma2(aG[0], F, W0); fma2(aG[1], F, W1);
        LOADP(4);
        F = Fv[2]; fma2(aV[0][0], F, W0); fma2(aV[0][1], F, W1);
        F = Fv[3]; fma2(aV[1][0], F, W0); fma2(aV[1][1], F, W1);
        F = Fv[4]; fma2(aV[2][0], F, W0); fma2(aV[2][1], F, W1);
        LOADP(5);
        F = Fv[5]; fma2(aV[0][0], F, W0); fma2(aV[0][1], F, W1);
        F = Fv[6]; fma2(aV[1][0], F, W0); fma2(aV[1][1], F, W1);
        F = Fv[7]; fma2(aV[2][0], F, W0); fma2(aV[2][1], F, W1);
        LOADP(6);
        F = Fv[8];  fma2(aV[0][0], F, W0); fma2(aV[0][1], F, W1);
        F = Fv[9];  fma2(aV[1][0], F, W0); fma2(aV[1][1], F, W1);
        F = Fv[10]; fma2(aV[2][0], F, W0); fma2(aV[2][1], F, W1);
#undef LOADP
    }

    float S[4], G[4], V[3][4];
    upk2(aS[0], S[0], S[1]); upk2(aS[1], S[2], S[3]);
    upk2(aG[0], G[0], G[1]); upk2(aG[1], G[2], G[3]);
    #pragma unroll
    for (int k = 0; k < 3; k++) {
        upk2(aV[k][0], V[k][0], V[k][1]);
        upk2(aV[k][1], V[k][2], V[k][3]);
    }

#define RED(v)                                                    \
    v += __shfl_down_sync(0xffffffffu, v, 16);                    \
    v += __shfl_down_sync(0xffffffffu, v, 8);
    #pragma unroll
    for (int q = 0; q < 4; q++) {
        RED(S[q]) RED(G[q]) RED(V[0][q]) RED(V[1][q]) RED(V[2][q])
    }

    if (us == 0) {
        float* na = g_nodeacc + (size_t)dn * 161;
        #pragma unroll
        for (int q = 0; q < 4; q++) {
            int w = wb + q;
            atomicAdd(na + w,              S[q]);
            atomicAdd(na + 32 + w,         G[q]);
            atomicAdd(na + 64 + 3 * w + 0, V[0][q]);
            atomicAdd(na + 64 + 3 * w + 1, V[1][q]);
            atomicAdd(na + 64 + 3 * w + 2, V[2][q]);
        }
        if (lane == 0) atomicAdd(na + 160, 1.0f);
    }
}

// ---------------- kernel 5: mean, gating, self-connection, norms ----------------
__global__ void k_node(const float* __restrict__ x, const float* __restrict__ Wss,
                       const float* __restrict__ Wsv, float* __restrict__ out, int N) {
    __shared__ float sx[8][128];
    const int warp = threadIdx.x >> 5, lane = threadIdx.x & 31;
    int n = blockIdx.x * 8 + warp;
    if (n >= N) return;

    const float4* xr = reinterpret_cast<const float4*>(x + (size_t)n * 128);
    reinterpret_cast<float4*>(&sx[warp][0])[lane] = xr[lane];
    __syncwarp();

    const float* na = g_nodeacc + (size_t)n * 161;
    float inv = 1.0f / fmaxf(na[160], 1.0f);
    float ms  = na[lane] * inv;
    float mg  = na[32 + lane] * inv;
    float mv0 = na[64 + 3 * lane + 0] * inv;
    float mv1 = na[64 + 3 * lane + 1] * inv;
    float mv2 = na[64 + 3 * lane + 2] * inv;

    float gs   = ms / (1.0f + expf(-ms));
    float gate = 1.0f / (1.0f + expf(-mg));
    float gv0 = mv0 * gate, gv1 = mv1 * gate, gv2 = mv2 * gate;

    float ds = 0.f, dv0 = 0.f, dv1 = 0.f, dv2 = 0.f;
    #pragma unroll 4
    for (int u = 0; u < 32; u++) {
        float su  = sx[warp][u];
        float vu0 = sx[warp][32 + 3 * u], vu1 = sx[warp][33 + 3 * u], vu2 = sx[warp][34 + 3 * u];
        float a = __ldg(&Wss[u * 32 + lane]);
        float b = __ldg(&Wsv[u * 32 + lane]);
        ds  = fmaf(su,  a, ds);
        dv0 = fmaf(vu0, b, dv0);
        dv1 = fmaf(vu1, b, dv1);
        dv2 = fmaf(vu2, b, dv2);
    }
    const float ism = 0.17677669529663687f;   // 1/sqrt(32)
    float hs  = gs  + ds  * ism;
    float hv0 = gv0 + dv0 * ism;
    float hv1 = gv1 + dv1 * ism;
    float hv2 = gv2 + dv2 * ism;

    out[(size_t)n * 64 + lane]      = sqrtf(hs * hs + 1e-12f);
    out[(size_t)n * 64 + 32 + lane] = sqrtf(hv0 * hv0 + hv1 * hv1 + hv2 * hv2 + 1e-12f);
}

// ---------------- launch ----------------
extern "C" void kernel_launch(void* const* d_in, const int* in_sizes, int n_in,
                              void* d_out, int out_size) {
    const float* x    = (const float*)d_in[0];
    const float* attr = (const float*)d_in[1];
    const float* len  = (const float*)d_in[2];
    const int*   src  = (const int*)d_in[3];
    const int*   dst  = (const int*)d_in[4];
    const float* Wfc1 = (const float*)d_in[5];
    const float* Wfc2 = (const float*)d_in[6];
    const float* Wss  = (const float*)d_in[7];
    const float* Wsv  = (const float*)d_in[8];
    float* out = (float*)d_out;

    int N = in_sizes[0] / 128;
    int E = in_sizes[2];

    dim3 bgrid(KNOTS / 16, 28);
    k_build<<<bgrid, 256>>>(Wfc1, Wfc2, len, E);                 // #1 (table + hist)
    k_scan<<<1, 32>>>();                                         // #2 (scan + bin reset)
    k_scatterzero<<<(E + 255) / 256, 256>>>(len, E, N * 161);    // #3 (scatter + acc zero)
    k_edge<<<(E + 7) / 8, 256>>>(x, attr, len, src, dst, E);     // #4 (profiled slot)
    k_node<<<(N + 7) / 8, 256>>>(x, Wss, Wsv, out, N);           // #5
}

// round 8
// speedup vs baseline: 1.1730x; 1.1730x over previous
#include <cuda_runtime.h>
#include <cuda_fp16.h>
#include <math.h>

#define KNOTS 64
#define WCOLS 7168          // 7 paths * 32 u * 32 w
#define MAXN  4096
#define MAXE  32768
#define PERM_SZ (MAXE + 80) // even-padding slack (<=64 pads) + tail

typedef unsigned long long ull;

// ---------------- scratch (device globals; no allocation allowed) ----------------
__device__ unsigned short g_wtab_raw[(size_t)KNOTS * WCOLS];  // fp16 table, scales folded in
__device__ float g_nodeacc[MAXN * 161];           // 160 sums + 1 count per node
__device__ int   g_binCount[KNOTS];               // self-resetting per launch
__device__ int   g_binCursor[KNOTS];
__device__ int   g_perm[PERM_SZ];

// ---------------- f32x2 helpers ----------------
__device__ __forceinline__ ull pk2(float lo, float hi) {
    ull r; asm("mov.b64 %0, {%1, %2};" : "=l"(r) : "f"(lo), "f"(hi)); return r;
}
__device__ __forceinline__ void upk2(ull v, float& lo, float& hi) {
    asm("mov.b64 {%0, %1}, %2;" : "=f"(lo), "=f"(hi) : "l"(v));
}
__device__ __forceinline__ void fma2(ull& d, ull a, ull b) {
    asm("fma.rn.f32x2 %0, %1, %2, %0;" : "+l"(d) : "l"(a), "l"(b));
}

__device__ __forceinline__ int cell_of(float L) {
    float t = L * ((float)(KNOTS - 1) / 5.0f);
    int i = (int)floorf(t);
    if (i < 0) i = 0;
    if (i > KNOTS - 2) i = KNOTS - 2;
    return i;
}

// ---------------- kernel 1: build fp16 W(r) table + low-contention histogram ----------------
__global__ void k_build(const float* __restrict__ Wfc1, const float* __restrict__ Wfc2,
                        const float* __restrict__ len, int E) {
    __shared__ float sm_h[64][17];
    __shared__ int   sm_hist[KNOTS];
    const int t = threadIdx.x;
    const int kbase = blockIdx.x * 16;
    const int col = blockIdx.y * 256 + t;

    if (t < KNOTS) sm_hist[t] = 0;
    __syncthreads();

    {
        int gid = (blockIdx.y * gridDim.x + blockIdx.x) * 256 + t;
        int stride = gridDim.x * gridDim.y * 256;
        for (int e = gid; e < E; e += stride)
            atomicAdd(&sm_hist[cell_of(len[e])], 1);
    }

    for (int idx = t; idx < 16 * 64; idx += 256) {
        int kk = idx >> 6, c = idx & 63;
        float r = (float)(kbase + kk) * (5.0f / (float)(KNOTS - 1));
        float pre = 0.0f;
        #pragma unroll
        for (int j = 0; j < 8; j++) {
            float d = r - (float)j * (5.0f / 7.0f);
            float rad = expf(-d * d * 0.98f);
            pre += rad * Wfc1[j * 64 + c];
        }
        pre *= 0.35355339059327373f;                    // 1/sqrt(8)
        sm_h[c][kk] = pre / (1.0f + expf(-pre));        // silu
    }
    __syncthreads();

    if (t < KNOTS && sm_hist[t] > 0) atomicAdd(&g_binCount[t], sm_hist[t]);

    float acc[16];
    #pragma unroll
    for (int kk = 0; kk < 16; kk++) acc[kk] = 0.0f;
    #pragma unroll 4
    for (int c = 0; c < 64; c++) {
        float wv = __ldg(&Wfc2[c * WCOLS + col]);
        #pragma unroll
        for (int kk = 0; kk < 16; kk++) acc[kk] = fmaf(sm_h[c][kk], wv, acc[kk]);
    }
    float sc = (col < 4096) ? 0.015625f : 0.022097086912079608f;
    #pragma unroll
    for (int kk = 0; kk < 16; kk++)
        g_wtab_raw[(size_t)(kbase + kk) * WCOLS + col] =
            __half_as_ushort(__float2half_rn(acc[kk] * sc));
}

// ---------------- kernel 2: scan with EVEN padding + pad sentinels + bin reset ----------------
__global__ void k_scan() {
    int t = threadIdx.x;
    int n0 = g_binCount[2 * t], n1 = g_binCount[2 * t + 1];
    int p0 = n0 + (n0 & 1), p1 = n1 + (n1 & 1);   // round up to even
    int s = p0 + p1;
    int x = s;
    #pragma unroll
    for (int o = 1; o < 32; o <<= 1) {
        int y = __shfl_up_sync(0xffffffffu, x, o);
        if (t >= o) x += y;
    }
    int excl = x - s;
    g_binCursor[2 * t]     = excl;
    g_binCursor[2 * t + 1] = excl + p0;
    if (n0 & 1) g_perm[excl + n0]      = -1;      // pad slot for odd bin
    if (n1 & 1) g_perm[excl + p0 + n1] = -1;
    int tot = __shfl_sync(0xffffffffu, x, 31);    // grand padded total
    for (int i = tot + t; i < PERM_SZ; i += 32) g_perm[i] = -1;
    g_binCount[2 * t] = 0;
    g_binCount[2 * t + 1] = 0;
}

// ---------------- kernel 3: two-level scatter + nodeacc zeroing ----------------
__global__ void k_scatterzero(const float* __restrict__ len, int E, int accTotal) {
    __shared__ int sCnt[KNOTS];
    __shared__ int sBase[KNOTS];
    const int t = threadIdx.x;
    const int gid = blockIdx.x * 256 + t;

    if (t < KNOTS) sCnt[t] = 0;

    for (int i = gid; i < accTotal; i += gridDim.x * 256) g_nodeacc[i] = 0.0f;
    __syncthreads();

    int e = -1, bin = 0, rank = 0;
    if (gid < E) {
        e = gid;
        bin = cell_of(len[e]);
        rank = atomicAdd(&sCnt[bin], 1);
    }
    __syncthreads();
    if (t < KNOTS) sBase[t] = (sCnt[t] > 0) ? atomicAdd(&g_binCursor[t], sCnt[t]) : 0;
    __syncthreads();
    if (e >= 0) g_perm[sBase[bin] + rank] = e;
}

// ---------------- kernel 4 (profiled slot): main edge kernel ----------------
// 1 warp per TWO same-cell edges. lanes 0-15: edge0, 16-31: edge1 (identical weight
// addresses -> L1 dedup). Per half: wg=lane&7 -> 4 w-cols, us=(lane>>3)&1 -> u=2j+us.
// fp16 table, fp16 lerp (hsub2+hfma2), f32x2 feature FMA.
__global__ __launch_bounds__(256, 3) void k_edge(
        const float* __restrict__ x, const float* __restrict__ attr,
        const float* __restrict__ len, const int* __restrict__ src,
        const int* __restrict__ dst, int E) {
    __shared__ float2 sF[8][2][383];   // [warp][edge][u*12+feat], (t,t) dup; conflict-free
    const int warp = threadIdx.x >> 5, lane = threadIdx.x & 31;
    int sbase = (blockIdx.x * 8 + warp) * 2;
    int e0 = g_perm[sbase];
    if (e0 < 0) return;
    int e1 = g_perm[sbase + 1];

    const float SC = (float)(KNOTS - 1) / 5.0f;
    float L0 = len[e0];
    int cell = cell_of(L0);
    float f0 = fminf(fmaxf(L0 * SC - (float)cell, 0.0f), 1.0f);
    int dn0 = dst[e0];
    float f1 = 0.0f; int dn1 = 0;
    if (e1 >= 0) {
        f1 = fminf(fmaxf(len[e1] * SC - (float)cell, 0.0f), 1.0f);
        dn1 = dst[e1];
    }

    // ---- features for both edges; lane = u ----
    const float cA = 0.31622776601683794f;   // 1/sqrt(10)
    const float cB = 0.18257418583505536f;   // 1/sqrt(30)
    const float cC = 0.36514837167011072f;   // 2/sqrt(30)
    const float IS3 = 0.5773502691896258f;
    #pragma unroll
    for (int el = 0; el < 2; el++) {
        int e = el ? e1 : e0;
        float F[11];
        #pragma unroll
        for (int k = 0; k < 11; k++) F[k] = 0.0f;
        if (e >= 0) {
            int sn = src[e];
            const float* ar = attr + e * 9;
            float y0  = ar[0];
            float y10 = ar[1], y11 = ar[2], y12 = ar[3];
            float y20 = ar[4], y21 = ar[5], y22 = ar[6], y23 = ar[7], y24 = ar[8];
            float M00 = -cB * y22 + cA * y24;
            float M01 =  cA * y20,  M02 = cA * y23;
            float M10 =  cA * y20,  M11 = -cB * y22 - cA * y24, M12 = cA * y21;
            float M20 =  cA * y23,  M21 = cA * y21,             M22 = cC * y22;
            const float* xr = x + (size_t)sn * 128;
            float sj = xr[lane];
            float v0 = xr[32 + 3 * lane], v1 = xr[33 + 3 * lane], v2 = xr[34 + 3 * lane];
            F[0] = sj * y0;
            F[1] = (v0 * y10 + v1 * y11 + v2 * y12) * IS3;
            float sy = sj * IS3;
            F[2] = sy * y10; F[3] = sy * y11; F[4] = sy * y12;
            float yv = y0 * IS3;
            F[5] = v0 * yv; F[6] = v1 * yv; F[7] = v2 * yv;
            F[8]  = v0 * M00 + v1 * M10 + v2 * M20;
            F[9]  = v0 * M01 + v1 * M11 + v2 * M21;
            F[10] = v0 * M02 + v1 * M12 + v2 * M22;
        }
        float2* fb = &sF[warp][el][lane * 12];
        #pragma unroll
        for (int k = 0; k < 11; k++) fb[k] = make_float2(F[k], F[k]);
    }
    __syncwarp();

    // per-lane lerp factor (own edge's f)
    float fe = (lane < 16) ? f0 : f1;
    __half2 fh2 = __floats2half2_rn(fe, fe);

    const __half* wt = reinterpret_cast<const __half*>(g_wtab_raw);
    const __half* r0base = wt + (size_t)cell * WCOLS;
    const __half* r1base = r0base + WCOLS;

    const int wb = (lane & 7) * 4;
    const int us = (lane >> 3) & 1;
    const int el = lane >> 4;

    ull aS[2]    = {0ull, 0ull};
    ull aG[2]    = {0ull, 0ull};
    ull aV[3][2] = {{0ull,0ull},{0ull,0ull},{0ull,0ull}};

    #pragma unroll 2
    for (int j = 0; j < 16; j++) {
        int u = 2 * j + us;
        const ull* Fu = reinterpret_cast<const ull*>(&sF[warp][el][u * 12]);
        int ub = u * 32 + wb;
        const __half* p0 = r0base + ub;
        const __half* p1 = r1base + ub;
        ull W0, W1, F;

#define LOADP(P)                                                                  \
        {                                                                         \
            uint2 _a = *reinterpret_cast<const uint2*>(p0 + (P) * 1024);          \
            uint2 _b = *reinterpret_cast<const uint2*>(p1 + (P) * 1024);          \
            __half2 _a0 = *reinterpret_cast<const __half2*>(&_a.x);               \
            __half2 _a1 = *reinterpret_cast<const __half2*>(&_a.y);               \
            __half2 _b0 = *reinterpret_cast<const __half2*>(&_b.x);               \
            __half2 _b1 = *reinterpret_cast<const __half2*>(&_b.y);               \
            __half2 _w0 = __hfma2(fh2, __hsub2(_b0, _a0), _a0);                   \
            __half2 _w1 = __hfma2(fh2, __hsub2(_b1, _a1), _a1);                   \
            float2 _f0 = __half22float2(_w0);                                     \
            float2 _f1 = __half22float2(_w1);                                     \
            W0 = pk2(_f0.x, _f0.y);                                               \
            W1 = pk2(_f1.x, _f1.y);                                               \
        }

        LOADP(0); F = Fu[0]; fma2(aS[0], F, W0); fma2(aS[1], F, W1);
        LOADP(1); F = Fu[1]; fma2(aS[0], F, W0); fma2(aS[1], F, W1);
        LOADP(2); F = Fu[0]; fma2(aG[0], F, W0); fma2(aG[1], F, W1);
        LOADP(3); F = Fu[1]; fma2(aG[0], F, W0); fma2(aG[1], F, W1);
        LOADP(4);
        F = Fu[2]; fma2(aV[0][0], F, W0); fma2(aV[0][1], F, W1);
        F = Fu[3]; fma2(aV[1][0], F, W0); fma2(aV[1][1], F, W1);
        F = Fu[4]; fma2(aV[2][0], F, W0); fma2(aV[2][1], F, W1);
        LOADP(5);
        F = Fu[5]; fma2(aV[0][0], F, W0); fma2(aV[0][1], F, W1);
        F = Fu[6]; fma2(aV[1][0], F, W0); fma2(aV[1][1], F, W1);
        F = Fu[7]; fma2(aV[2][0], F, W0); fma2(aV[2][1], F, W1);
        LOADP(6);
        F = Fu[8];  fma2(aV[0][0], F, W0); fma2(aV[0][1], F, W1);
        F = Fu[9];  fma2(aV[1][0], F, W0); fma2(aV[1][1], F, W1);
        F = Fu[10]; fma2(aV[2][0], F, W0); fma2(aV[2][1], F, W1);
#undef LOADP
    }

    float S[4], G[4], V[3][4];
    upk2(aS[0], S[0], S[1]); upk2(aS[1], S[2], S[3]);
    upk2(aG[0], G[0], G[1]); upk2(aG[1], G[2], G[3]);
    #pragma unroll
    for (int k = 0; k < 3; k++) {
        upk2(aV[k][0], V[k][0], V[k][1]);
        upk2(aV[k][1], V[k][2], V[k][3]);
    }

    // reduce over us (lanes +8) within each 16-lane half
#define RED(v) v += __shfl_down_sync(0xffffffffu, v, 8, 16);
    #pragma unroll
    for (int q = 0; q < 4; q++) {
        RED(S[q]) RED(G[q]) RED(V[0][q]) RED(V[1][q]) RED(V[2][q])
    }

    if ((lane & 8) == 0) {     // us==0 lanes: 0-7 (edge0), 16-23 (edge1)
        int eL = (lane < 16) ? e0 : e1;
        if (eL >= 0) {
            int dnL = (lane < 16) ? dn0 : dn1;
            float* na = g_nodeacc + (size_t)dnL * 161;
            #pragma unroll
            for (int q = 0; q < 4; q++) {
                int w = wb + q;
                atomicAdd(na + w,              S[q]);
                atomicAdd(na + 32 + w,         G[q]);
                atomicAdd(na + 64 + 3 * w + 0, V[0][q]);
                atomicAdd(na + 64 + 3 * w + 1, V[1][q]);
                atomicAdd(na + 64 + 3 * w + 2, V[2][q]);
            }
            if ((lane & 15) == 0) atomicAdd(na + 160, 1.0f);
        }
    }
}

// ---------------- kernel 5: mean, gating, self-connection, norms ----------------
__global__ void k_node(const float* __restrict__ x, const float* __restrict__ Wss,
                       const float* __restrict__ Wsv, float* __restrict__ out, int N) {
    __shared__ float sx[8][128];
    const int warp = threadIdx.x >> 5, lane = threadIdx.x & 31;
    int n = blockIdx.x * 8 + warp;
    if (n >= N) return;

    const float4* xr = reinterpret_cast<const float4*>(x + (size_t)n * 128);
    reinterpret_cast<float4*>(&sx[warp][0])[lane] = xr[lane];
    __syncwarp();

    const float* na = g_nodeacc + (size_t)n * 161;
    float inv = 1.0f / fmaxf(na[160], 1.0f);
    float ms  = na[lane] * inv;
    float mg  = na[32 + lane] * inv;
    float mv0 = na[64 + 3 * lane + 0] * inv;
    float mv1 = na[64 + 3 * lane + 1] * inv;
    float mv2 = na[64 + 3 * lane + 2] * inv;

    float gs   = ms / (1.0f + expf(-ms));
    float gate = 1.0f / (1.0f + expf(-mg));
    float gv0 = mv0 * gate, gv1 = mv1 * gate, gv2 = mv2 * gate;

    float ds = 0.f, dv0 = 0.f, dv1 = 0.f, dv2 = 0.f;
    #pragma unroll 4
    for (int u = 0; u < 32; u++) {
        float su  = sx[warp][u];
        float vu0 = sx[warp][32 + 3 * u], vu1 = sx[warp][33 + 3 * u], vu2 = sx[warp][34 + 3 * u];
        float a = __ldg(&Wss[u * 32 + lane]);
        float b = __ldg(&Wsv[u * 32 + lane]);
        ds  = fmaf(su,  a, ds);
        dv0 = fmaf(vu0, b, dv0);
        dv1 = fmaf(vu1, b, dv1);
        dv2 = fmaf(vu2, b, dv2);
    }
    const float ism = 0.17677669529663687f;   // 1/sqrt(32)
    float hs  = gs  + ds  * ism;
    float hv0 = gv0 + dv0 * ism;
    float hv1 = gv1 + dv1 * ism;
    float hv2 = gv2 + dv2 * ism;

    out[(size_t)n * 64 + lane]      = sqrtf(hs * hs + 1e-12f);
    out[(size_t)n * 64 + 32 + lane] = sqrtf(hv0 * hv0 + hv1 * hv1 + hv2 * hv2 + 1e-12f);
}

// ---------------- launch ----------------
extern "C" void kernel_launch(void* const* d_in, const int* in_sizes, int n_in,
                              void* d_out, int out_size) {
    const float* x    = (const float*)d_in[0];
    const float* attr = (const float*)d_in[1];
    const float* len  = (const float*)d_in[2];
    const int*   src  = (const int*)d_in[3];
    const int*   dst  = (const int*)d_in[4];
    const float* Wfc1 = (const float*)d_in[5];
    const float* Wfc2 = (const float*)d_in[6];
    const float* Wss  = (const float*)d_in[7];
    const float* Wsv  = (const float*)d_in[8];
    float* out = (float*)d_out;

    int N = in_sizes[0] / 128;
    int E = in_sizes[2];

    dim3 bgrid(KNOTS / 16, 28);
    k_build<<<bgrid, 256>>>(Wfc1, Wfc2, len, E);                 // #1 (table + hist)
    k_scan<<<1, 32>>>();                                         // #2 (even-pad scan)
    k_scatterzero<<<(E + 255) / 256, 256>>>(len, E, N * 161);    // #3 (scatter + acc zero)
    k_edge<<<(PERM_SZ + 15) / 16, 256>>>(x, attr, len, src, dst, E);  // #4 (profiled)
    k_node<<<(N + 7) / 8, 256>>>(x, Wss, Wsv, out, N);           // #5
}

// round 9
// speedup vs baseline: 1.5352x; 1.3087x over previous
#include <cuda_runtime.h>
#include <cuda_fp16.h>
#include <math.h>

#define KNOTS 64
#define WCOLS 7168          // 7 paths * 32 u * 32 w
#define MAXN  4096
#define MAXE  32768
#define NCELLS 63           // cell_of in [0,62]
#define PERM_SZ (MAXE + 16 * 64)   // per-cell pad to mult of 16
#define NTILES  (PERM_SZ / 16)     // 2112

// B layouts (halfs), rows padded for conflict-free fragment LDS
#define ST_SG 136           // K=128 + 8 pad
#define ST_V  200           // K=192 + 8 pad
#define BSG_CELL (64 * ST_SG)   // 8704 halfs
#define BV_CELL  (32 * ST_V)    // 6400 halfs

// ---------------- scratch (device globals; no allocation allowed) ----------------
__device__ __align__(16) __half g_Bsg[64 * BSG_CELL];   // [cell][n=64][k=128 pad 136]
__device__ __align__(16) __half g_Bv [64 * BV_CELL];    // [cell][n=32][k=192 pad 200]
__device__ float g_nodeacc[MAXN * 161];
__device__ int   g_binCount[64];
__device__ int   g_binCursor[64];
__device__ int   g_perm[PERM_SZ];
__device__ int   g_tileCell[NTILES];

__device__ __forceinline__ int cell_of(float L) {
    float t = L * ((float)(KNOTS - 1) / 5.0f);
    int i = (int)floorf(t);
    if (i < 0) i = 0;
    if (i > KNOTS - 2) i = KNOTS - 2;
    return i;
}

// ---------------- kernel 1: build per-cell B matrices + histogram ----------------
// Grid (4, 28), block 256: 16 knot-rows x 256 cols each.
__global__ void k_build(const float* __restrict__ Wfc1, const float* __restrict__ Wfc2,
                        const float* __restrict__ len, int E) {
    __shared__ float sm_h[64][17];
    __shared__ int   sm_hist[64];
    const int t = threadIdx.x;
    const int kbase = blockIdx.x * 16;
    const int col = blockIdx.y * 256 + t;

    if (t < 64) sm_hist[t] = 0;
    __syncthreads();

    {
        int gid = (blockIdx.y * gridDim.x + blockIdx.x) * 256 + t;
        int stride = gridDim.x * gridDim.y * 256;
        for (int e = gid; e < E; e += stride)
            atomicAdd(&sm_hist[cell_of(len[e])], 1);
    }

    for (int idx = t; idx < 16 * 64; idx += 256) {
        int kk = idx >> 6, c = idx & 63;
        float r = (float)(kbase + kk) * (5.0f / (float)(KNOTS - 1));
        float pre = 0.0f;
        #pragma unroll
        for (int j = 0; j < 8; j++) {
            float d = r - (float)j * (5.0f / 7.0f);
            float rad = expf(-d * d * 0.98f);
            pre += rad * Wfc1[j * 64 + c];
        }
        pre *= 0.35355339059327373f;                 // 1/sqrt(8)
        sm_h[c][kk] = pre / (1.0f + expf(-pre));     // silu
    }
    __syncthreads();

    if (t < 64 && sm_hist[t] > 0) atomicAdd(&g_binCount[t], sm_hist[t]);

    float acc[16];
    #pragma unroll
    for (int kk = 0; kk < 16; kk++) acc[kk] = 0.0f;
    #pragma unroll 4
    for (int c = 0; c < 64; c++) {
        float wv = __ldg(&Wfc2[c * WCOLS + col]);
        #pragma unroll
        for (int kk = 0; kk < 16; kk++) acc[kk] = fmaf(sm_h[c][kk], wv, acc[kk]);
    }
    float sc = (col < 4096) ? 0.015625f : 0.022097086912079608f;

    const int p = col >> 10, u = (col >> 5) & 31, w = col & 31;
    #pragma unroll
    for (int kk = 0; kk < 16; kk++) {
        __half hv = __float2half_rn(acc[kk] * sc);
        int row = kbase + kk;
        if (p < 4) {
            int n = (p >> 1) * 32 + w;         // S cols 0-31, G cols 32-63
            int kb = (p & 1) * 32 + u;         // feat*32 + u
            if (row <= 62) g_Bsg[(size_t)row * BSG_CELL + n * ST_SG + kb] = hv;        // knot0
            if (row >= 1)  g_Bsg[(size_t)(row - 1) * BSG_CELL + n * ST_SG + 64 + kb] = hv;  // knot1
        } else {
            int kb = (p - 4) * 32 + u;
            if (row <= 62) g_Bv[(size_t)row * BV_CELL + w * ST_V + kb] = hv;
            if (row >= 1)  g_Bv[(size_t)(row - 1) * BV_CELL + w * ST_V + 96 + kb] = hv;
        }
    }
}

// ---------------- kernel 2: scan (pad-16) + tile map + bin reset ----------------
__global__ void k_scan() {
    int t = threadIdx.x;   // 32
    int c0 = 2 * t, c1 = 2 * t + 1;
    int n0 = (c0 < NCELLS) ? g_binCount[c0] : 0;
    int n1 = (c1 < NCELLS) ? g_binCount[c1] : 0;
    int p0 = (n0 + 15) & ~15, p1 = (n1 + 15) & ~15;
    int s = p0 + p1;
    int x = s;
    #pragma unroll
    for (int o = 1; o < 32; o <<= 1) {
        int y = __shfl_up_sync(0xffffffffu, x, o);
        if (t >= o) x += y;
    }
    int base0 = x - s;
    int base1 = base0 + p0;
    g_binCursor[c0] = base0;
    g_binCursor[c1] = base1;
    for (int i = n0; i < p0; i++) g_perm[base0 + i] = -1;
    for (int i = n1; i < p1; i++) g_perm[base1 + i] = -1;
    for (int i = 0; i < (p0 >> 4); i++) g_tileCell[(base0 >> 4) + i] = c0;
    for (int i = 0; i < (p1 >> 4); i++) g_tileCell[(base1 >> 4) + i] = c1;
    int tot = __shfl_sync(0xffffffffu, x, 31);
    for (int i = (tot >> 4) + t; i < NTILES; i += 32) g_tileCell[i] = -1;
    g_binCount[c0] = 0;
    g_binCount[c1] = 0;
}

// ---------------- kernel 3: two-level scatter + nodeacc zeroing ----------------
__global__ void k_scatterzero(const float* __restrict__ len, int E, int accTotal) {
    __shared__ int sCnt[64];
    __shared__ int sBase[64];
    const int t = threadIdx.x;
    const int gid = blockIdx.x * 256 + t;

    if (t < 64) sCnt[t] = 0;

    for (int i = gid; i < accTotal; i += gridDim.x * 256) g_nodeacc[i] = 0.0f;
    __syncthreads();

    int e = -1, bin = 0, rank = 0;
    if (gid < E) {
        e = gid;
        bin = cell_of(len[e]);
        rank = atomicAdd(&sCnt[bin], 1);
    }
    __syncthreads();
    if (t < 64) sBase[t] = (sCnt[t] > 0) ? atomicAdd(&g_binCursor[t], sCnt[t]) : 0;
    __syncthreads();
    if (e >= 0) g_perm[sBase[bin] + rank] = e;
}

// ---------------- kernel 4 (profiled slot): tensor-core edge kernel ----------------
// CTA = 1 tile = 16 same-cell edges. fp16 A built in smem (lerp folded into features),
// B staged from per-cell global; 20 m16n8k16 work items over 8 warps; C -> atomics.
// smem halfs: A_sg[16*136]=2176 | A_v[48*200]=9600 | B_sg[64*136]=8704 | B_v[32*200]=6400
#define OFF_AV  2176
#define OFF_BSG 11776
#define OFF_BV  20480
#define SMEM_HALFS 26880
#define SMEM_BYTES (SMEM_HALFS * 2 + 128)

__global__ __launch_bounds__(256, 4) void k_edge_mma(
        const float* __restrict__ x, const float* __restrict__ attr,
        const float* __restrict__ len, const int* __restrict__ src,
        const int* __restrict__ dst) {
    extern __shared__ __align__(16) __half smh[];
    __half* sAsg = smh;
    __half* sAv  = smh + OFF_AV;
    __half* sBsg = smh + OFF_BSG;
    __half* sBv  = smh + OFF_BV;
    int* sEdge = (int*)(smh + SMEM_HALFS);
    int* sDst  = sEdge + 16;

    const int tile = blockIdx.x;
    const int cell = g_tileCell[tile];
    if (cell < 0) return;
    const int t = threadIdx.x;
    const int lane = t & 31, warp = t >> 5;

    // ---- stage B (coalesced) ----
    {
        const uint4* gb = (const uint4*)(g_Bsg + (size_t)cell * BSG_CELL);
        uint4* sb = (uint4*)sBsg;
        for (int i = t; i < BSG_CELL / 8; i += 256) sb[i] = gb[i];
        const uint4* gv = (const uint4*)(g_Bv + (size_t)cell * BV_CELL);
        uint4* sv = (uint4*)sBv;
        for (int i = t; i < BV_CELL / 8; i += 256) sv[i] = gv[i];
    }

    // ---- feature phase: thread t -> edge e = t>>4, u in {t&15, (t&15)+16} ----
    {
        const int e = t >> 4, u0 = t & 15;
        int eg = g_perm[tile * 16 + e];
        float f = 0.0f;
        float y0 = 0, y10 = 0, y11 = 0, y12 = 0;
        float M00 = 0, M01 = 0, M02 = 0, M10 = 0, M11 = 0, M12 = 0, M20 = 0, M21 = 0, M22 = 0;
        const float* xr = x;   // dummy
        if (eg >= 0) {
            float L = len[eg];
            float tp = L * ((float)(KNOTS - 1) / 5.0f) - (float)cell;
            f = fminf(fmaxf(tp, 0.0f), 1.0f);
            const float* ar = attr + eg * 9;
            y0 = ar[0]; y10 = ar[1]; y11 = ar[2]; y12 = ar[3];
            float y20 = ar[4], y21 = ar[5], y22 = ar[6], y23 = ar[7], y24 = ar[8];
            const float cA = 0.31622776601683794f;
            const float cB = 0.18257418583505536f;
            const float cC = 0.36514837167011072f;
            M00 = -cB * y22 + cA * y24;
            M01 =  cA * y20;  M02 = cA * y23;
            M10 =  cA * y20;  M11 = -cB * y22 - cA * y24;  M12 = cA * y21;
            M20 =  cA * y23;  M21 = cA * y21;              M22 = cC * y22;
            xr = x + (size_t)src[eg] * 128;
        }
        float g1 = 1.0f - f;
        if (u0 == 0) {
            sEdge[e] = eg;
            int dn = (eg >= 0) ? dst[eg] : 0;
            sDst[e] = dn;
            if (eg >= 0) atomicAdd(g_nodeacc + (size_t)dn * 161 + 160, 1.0f);
        }
        const float IS3 = 0.5773502691896258f;
        #pragma unroll
        for (int half_ = 0; half_ < 2; half_++) {
            int u = u0 + half_ * 16;
            float F[11];
            #pragma unroll
            for (int k = 0; k < 11; k++) F[k] = 0.0f;
            if (eg >= 0) {
                float sj = xr[u];
                float v0 = xr[32 + 3 * u], v1 = xr[33 + 3 * u], v2 = xr[34 + 3 * u];
                F[0] = sj * y0;
                F[1] = (v0 * y10 + v1 * y11 + v2 * y12) * IS3;
                float sy = sj * IS3;
                F[2] = sy * y10; F[3] = sy * y11; F[4] = sy * y12;
                float yv = y0 * IS3;
                F[5] = v0 * yv; F[6] = v1 * yv; F[7] = v2 * yv;
                F[8]  = v0 * M00 + v1 * M10 + v2 * M20;
                F[9]  = v0 * M01 + v1 * M11 + v2 * M21;
                F[10] = v0 * M02 + v1 * M12 + v2 * M22;
            }
            __half* asg = sAsg + e * ST_SG;
            asg[u]      = __float2half_rn(F[0] * g1);
            asg[32 + u] = __float2half_rn(F[1] * g1);
            asg[64 + u] = __float2half_rn(F[0] * f);
            asg[96 + u] = __float2half_rn(F[1] * f);
            #pragma unroll
            for (int kc = 0; kc < 3; kc++) {
                __half* av = sAv + (kc * 16 + e) * ST_V;
                av[u]        = __float2half_rn(F[2 + kc] * g1);   // t01 -> path4
                av[32 + u]   = __float2half_rn(F[5 + kc] * g1);   // t10 -> path5
                av[64 + u]   = __float2half_rn(F[8 + kc] * g1);   // t12 -> path6
                av[96 + u]   = __float2half_rn(F[2 + kc] * f);
                av[128 + u]  = __float2half_rn(F[5 + kc] * f);
                av[160 + u]  = __float2half_rn(F[8 + kc] * f);
            }
        }
    }
    __syncthreads();

    // ---- MMA phase: 20 work items (8 S&G n-tiles, 12 V (m,n)-tiles) over 8 warps ----
    const int r0 = lane >> 2;           // fragment row group
    const int cp = (lane & 3) * 2;      // fragment col pair
    for (int item = warp; item < 20; item += 8) {
        float c0 = 0.f, c1 = 0.f, c2 = 0.f, c3 = 0.f;
        const __half *A, *B;
        int K, stA, nb;
        int isV = (item >= 8);
        int kcomp = 0, wbase = 0;
        if (!isV) {
            A = sAsg; B = sBsg; K = 8; stA = ST_SG; nb = item * 8;
        } else {
            int idx = item - 8;
            kcomp = idx >> 2;
            int nt = idx & 3;
            A = sAv + kcomp * 16 * ST_V; B = sBv; K = 12; stA = ST_V; nb = nt * 8;
            wbase = nt * 8;
        }
        const int stB = stA;  // same padded stride per matrix family
        for (int ks = 0; ks < K; ks++) {
            int kb = ks * 16;
            unsigned a0 = *(const unsigned*)(A + r0 * stA + kb + cp);
            unsigned a1 = *(const unsigned*)(A + (r0 + 8) * stA + kb + cp);
            unsigned a2 = *(const unsigned*)(A + r0 * stA + kb + 8 + cp);
            unsigned a3 = *(const unsigned*)(A + (r0 + 8) * stA + kb + 8 + cp);
            unsigned b0 = *(const unsigned*)(B + (nb + r0) * stB + kb + cp);
            unsigned b1 = *(const unsigned*)(B + (nb + r0) * stB + kb + 8 + cp);
            asm volatile(
                "mma.sync.aligned.m16n8k16.row.col.f32.f16.f16.f32 "
                "{%0,%1,%2,%3}, {%4,%5,%6,%7}, {%8,%9}, {%0,%1,%2,%3};\n"
                : "+f"(c0), "+f"(c1), "+f"(c2), "+f"(c3)
                : "r"(a0), "r"(a1), "r"(a2), "r"(a3), "r"(b0), "r"(b1));
        }
        // epilogue: C[r][n] -> atomics. rows r0, r0+8 = edges; cols cp, cp+1.
        int ed0 = sEdge[r0], ed1 = sEdge[r0 + 8];
        float* na0 = g_nodeacc + (size_t)sDst[r0] * 161;
        float* na1 = g_nodeacc + (size_t)sDst[r0 + 8] * 161;
        if (!isV) {
            int nc = item * 8 + cp;        // 0-31 = S, 32-63 = G (matches nodeacc)
            if (ed0 >= 0) { atomicAdd(na0 + nc, c0); atomicAdd(na0 + nc + 1, c1); }
            if (ed1 >= 0) { atomicAdd(na1 + nc, c2); atomicAdd(na1 + nc + 1, c3); }
        } else {
            int w = wbase + cp;
            if (ed0 >= 0) {
                atomicAdd(na0 + 64 + 3 * w + kcomp,       c0);
                atomicAdd(na0 + 64 + 3 * (w + 1) + kcomp, c1);
            }
            if (ed1 >= 0) {
                atomicAdd(na1 + 64 + 3 * w + kcomp,       c2);
                atomicAdd(na1 + 64 + 3 * (w + 1) + kcomp, c3);
            }
        }
    }
}

// ---------------- kernel 5: mean, gating, self-connection, norms ----------------
__global__ void k_node(const float* __restrict__ x, const float* __restrict__ Wss,
                       const float* __restrict__ Wsv, float* __restrict__ out, int N) {
    __shared__ float sx[8][128];
    const int warp = threadIdx.x >> 5, lane = threadIdx.x & 31;
    int n = blockIdx.x * 8 + warp;
    if (n >= N) return;

    const float4* xr = reinterpret_cast<const float4*>(x + (size_t)n * 128);
    reinterpret_cast<float4*>(&sx[warp][0])[lane] = xr[lane];
    __syncwarp();

    const float* na = g_nodeacc + (size_t)n * 161;
    float inv = 1.0f / fmaxf(na[160], 1.0f);
    float ms  = na[lane] * inv;
    float mg  = na[32 + lane] * inv;
    float mv0 = na[64 + 3 * lane + 0] * inv;
    float mv1 = na[64 + 3 * lane + 1] * inv;
    float mv2 = na[64 + 3 * lane + 2] * inv;

    float gs   = ms / (1.0f + expf(-ms));
    float gate = 1.0f / (1.0f + expf(-mg));
    float gv0 = mv0 * gate, gv1 = mv1 * gate, gv2 = mv2 * gate;

    float ds = 0.f, dv0 = 0.f, dv1 = 0.f, dv2 = 0.f;
    #pragma unroll 4
    for (int u = 0; u < 32; u++) {
        float su  = sx[warp][u];
        float vu0 = sx[warp][32 + 3 * u], vu1 = sx[warp][33 + 3 * u], vu2 = sx[warp][34 + 3 * u];
        float a = __ldg(&Wss[u * 32 + lane]);
        float b = __ldg(&Wsv[u * 32 + lane]);
        ds  = fmaf(su,  a, ds);
        dv0 = fmaf(vu0, b, dv0);
        dv1 = fmaf(vu1, b, dv1);
        dv2 = fmaf(vu2, b, dv2);
    }
    const float ism = 0.17677669529663687f;   // 1/sqrt(32)
    float hs  = gs  + ds  * ism;
    float hv0 = gv0 + dv0 * ism;
    float hv1 = gv1 + dv1 * ism;
    float hv2 = gv2 + dv2 * ism;

    out[(size_t)n * 64 + lane]      = sqrtf(hs * hs + 1e-12f);
    out[(size_t)n * 64 + 32 + lane] = sqrtf(hv0 * hv0 + hv1 * hv1 + hv2 * hv2 + 1e-12f);
}

// ---------------- launch ----------------
extern "C" void kernel_launch(void* const* d_in, const int* in_sizes, int n_in,
                              void* d_out, int out_size) {
    const float* x    = (const float*)d_in[0];
    const float* attr = (const float*)d_in[1];
    const float* len  = (const float*)d_in[2];
    const int*   src  = (const int*)d_in[3];
    const int*   dst  = (const int*)d_in[4];
    const float* Wfc1 = (const float*)d_in[5];
    const float* Wfc2 = (const float*)d_in[6];
    const float* Wss  = (const float*)d_in[7];
    const float* Wsv  = (const float*)d_in[8];
    float* out = (float*)d_out;

    int N = in_sizes[0] / 128;
    int E = in_sizes[2];

    cudaFuncSetAttribute(k_edge_mma, cudaFuncAttributeMaxDynamicSharedMemorySize, SMEM_BYTES);

    dim3 bgrid(KNOTS / 16, 28);
    k_build<<<bgrid, 256>>>(Wfc1, Wfc2, len, E);                 // #1 (B matrices + hist)
    k_scan<<<1, 32>>>();                                         // #2 (pad-16 scan + tiles)
    k_scatterzero<<<(E + 255) / 256, 256>>>(len, E, N * 161);    // #3 (scatter + acc zero)
    k_edge_mma<<<NTILES, 256, SMEM_BYTES>>>(x, attr, len, src, dst);  // #4 (profiled)
    k_node<<<(N + 7) / 8, 256>>>(x, Wss, Wsv, out, N);           // #5
}